// round 6
// baseline (speedup 1.0000x reference)
#include <cuda_runtime.h>
#include <cstdint>

#define CRF_B 512
#define CRF_S 512
#define CRF_T 64

// Per-batch partial results + completion ticket (device scratch; no allocs).
__device__ float    g_dpart[CRF_B];
__device__ float    g_npart[CRF_B];
__device__ unsigned g_ticket;   // zero-init; reset by last CTA each run

typedef unsigned long long u64;

// ---- packed f32x2 helpers (sm_100+ PTX) ----
__device__ __forceinline__ u64 ffma2(u64 a, u64 b, u64 c) {
    u64 d;
    asm("fma.rn.f32x2 %0, %1, %2, %3;" : "=l"(d) : "l"(a), "l"(b), "l"(c));
    return d;
}
__device__ __forceinline__ u64 fadd2(u64 a, u64 b) {
    u64 d;
    asm("add.rn.f32x2 %0, %1, %2;" : "=l"(d) : "l"(a), "l"(b));
    return d;
}
__device__ __forceinline__ u64 pack2(float x, float y) {
    u64 d;
    asm("mov.b64 %0, {%1, %2};" : "=l"(d) : "f"(x), "f"(y));
    return d;
}
__device__ __forceinline__ float2 unpack2(u64 a) {
    float2 r;
    asm("mov.b64 {%0, %1}, %2;" : "=f"(r.x), "=f"(r.y) : "l"(a));
    return r;
}

// Warp-uniform layout detection (ballot => uniform, no global state).
__device__ __forceinline__ int detect_mshift(const void* mask, int l) {
    const unsigned* mw = (const unsigned*)mask;
    unsigned bad = ((mw[l] | mw[l + 32]) & 0xFFFFFF00u) ? 1u : 0u;
    return __ballot_sync(0xffffffffu, bad) ? 0 : 2;   // u8 : i32
}
__device__ __forceinline__ int detect_tshift(const void* tags, int l) {
    const unsigned* tw = (const unsigned*)tags;
    unsigned odd = tw[2 * l + 1] ? 1u : 0u;
    return __ballot_sync(0xffffffffu, odd) ? 0 : 1;   // i32 : i64
}

// ============================================================================
// Single fused kernel: 128 blocks x 128 threads; warp w handles batch
// 4*blockIdx.x + w completely (forward denominator, then gold-path numerator).
// Last CTA to finish performs the final deterministic reduction.
//
// Forward: lane l owns states j=2l,2l+1; E=exp(trans) in registers (64 f32x2);
// p in per-warp ping-pong smem duplicated ({p,p}) so broadcast LDS.128 feeds
// fma.rn.f32x2. Exp-domain with LAZY power-of-2 renorm: the scale computed at
// step s (off the critical path) is folded into the next applied step's
// exp(logit) factor ONCE (apply-and-clear), with matching C adjustment.
// ============================================================================
__global__ void __launch_bounds__(128, 1) crf_main(
    const float* __restrict__ logits,
    const void* __restrict__ tagsv,
    const void* __restrict__ maskv,
    const float* __restrict__ trans,
    const float* __restrict__ startT,
    const float* __restrict__ endT,
    float* __restrict__ out)
{
    __shared__ __align__(16) u64 pdup[4][2][CRF_T];
    __shared__ float rbuf[128];
    __shared__ int   do_red;

    const int tid = threadIdx.x;
    const int w   = tid >> 5;
    const int l   = tid & 31;
    const int b   = blockIdx.x * 4 + w;

    const int msh = detect_mshift(maskv, l);
    const int tsh = detect_tshift(tagsv, l);

    // ---- E column pair for this lane, all 64 rows, in registers ----
    u64 Ereg[64];
#pragma unroll
    for (int i = 0; i < 64; i++) {
        float2 t = ((const float2*)trans)[i * 32 + l];
        Ereg[i] = pack2(__expf(t.x), __expf(t.y));
    }

    const float*         lg = logits + (size_t)b * (CRF_S * CRF_T);
    const unsigned char* mk = (const unsigned char*)maskv + (((size_t)b * CRF_S) << msh);

    // ---- init: alpha0 = start + logits[:,0,:]; exp-domain with offset C ----
    float2 l0 = ((const float2*)lg)[l];
    float a0 = startT[2 * l]     + l0.x;
    float a1 = startT[2 * l + 1] + l0.y;
    float mx = fmaxf(a0, a1);
#pragma unroll
    for (int o = 16; o; o >>= 1) mx = fmaxf(mx, __shfl_xor_sync(0xffffffffu, mx, o));
    float C  = mx;
    float p0 = __expf(a0 - mx);
    float p1 = __expf(a1 - mx);
    ((ulonglong2*)pdup[w][0])[l] = make_ulonglong2(pack2(p0, p0), pack2(p1, p1));

    // ---- prologue: 4-deep logits/mask register FIFO + current-step exp ----
    float2 f1 = ((const float2*)(lg + 1 * CRF_T))[l];
    float2 f2 = ((const float2*)(lg + 2 * CRF_T))[l];
    float2 f3 = ((const float2*)(lg + 3 * CRF_T))[l];
    float2 f4 = ((const float2*)(lg + 4 * CRF_T))[l];
    float2 f5 = ((const float2*)(lg + 5 * CRF_T))[l];
    unsigned char m2 = mk[(size_t)2 << msh];
    unsigned char m3 = mk[(size_t)3 << msh];
    unsigned char m4 = mk[(size_t)4 << msh];
    unsigned char m5 = mk[(size_t)5 << msh];
    float e0 = __expf(f1.x);
    float e1 = __expf(f1.y);
    unsigned char cm = mk[(size_t)1 << msh];

    float ps = 1.0f;   // pending power-of-2 scale (applied ONCE, then cleared)
    float pc = 0.0f;   // matching C delta, added when scale is applied
    __syncwarp();

#pragma unroll 4
    for (int s = 1; s < CRF_S; s++) {
        // GEMV over all 64 states: 16 broadcast LDS.128, 64 FFMA2, 4 chains.
        const ulonglong2* pd2 = (const ulonglong2*)pdup[w][(s - 1) & 1];
        u64 a0v = 0ull, a1v = 0ull, a2v = 0ull, a3v = 0ull;
#pragma unroll
        for (int k = 0; k < 64; k += 4) {
            ulonglong2 q0 = pd2[(k >> 1) + 0];
            ulonglong2 q1 = pd2[(k >> 1) + 1];
            a0v = ffma2(Ereg[k + 0], q0.x, a0v);
            a1v = ffma2(Ereg[k + 1], q0.y, a1v);
            a2v = ffma2(Ereg[k + 2], q1.x, a2v);
            a3v = ffma2(Ereg[k + 3], q1.y, a3v);
        }

        // FIFO rotate (renamed away by the unroll) + clamped prefetch.
        const float2 head        = f2;
        const unsigned char mh   = m2;
        f2 = f3; m2 = m3;
        f3 = f4; m3 = m4;
        f4 = f5; m4 = m5;
        const int sp = (s + 5 < CRF_S) ? (s + 5) : (CRF_S - 1);
        f5 = ((const float2*)(lg + (size_t)sp * CRF_T))[l];
        m5 = mk[(size_t)sp << msh];
        const float ne0 = __expf(head.x);
        const float ne1 = __expf(head.y);

        u64 tot    = fadd2(fadd2(a0v, a1v), fadd2(a2v, a3v));
        float2 sum = unpack2(tot);
        const float pn0 = sum.x * e0 * ps;
        const float pn1 = sum.y * e1 * ps;
        if (cm) {                       // mask: keep old alpha if 0
            p0 = pn0; p1 = pn1; C += pc;
            ps = 1.0f; pc = 0.0f;       // apply-and-clear (once!)
        }

        ((ulonglong2*)pdup[w][s & 1])[l] =
            make_ulonglong2(pack2(p0, p0), pack2(p1, p1));
        __syncwarp();

        // Refresh pending scale every 4 steps (off the critical path: consumed
        // one step later). Exact power-of-2 => no rounding. If a prior pending
        // was never applied (masked steps), recomputing from the current
        // exponent supersedes it correctly.
        if ((s & 3) == 0) {
            float m = fmaxf(p0, p1);
#pragma unroll
            for (int o = 16; o; o >>= 1)
                m = fmaxf(m, __shfl_xor_sync(0xffffffffu, m, o));
            const int ex = (__float_as_int(m) >> 23) & 255;
            ps = __int_as_float((254 - ex) << 23);             // 2^(127-ex)
            pc = (float)(ex - 127) * 0.6931471805599453f;
        }

        e0 = ne0; e1 = ne1; cm = mh;
    }

    // denom = C + log(sum_j p_j * exp(end_j))
    {
        float v = p0 * __expf(endT[2 * l]) + p1 * __expf(endT[2 * l + 1]);
#pragma unroll
        for (int o = 16; o; o >>= 1) v += __shfl_xor_sync(0xffffffffu, v, o);
        if (l == 0) g_dpart[b] = C + logf(v);
    }

    // ---- numerator (gold-path score) for the same batch ----
    {
        const int*           tg  = (const int*)tagsv;
        const unsigned char* mkp = (const unsigned char*)maskv;
        const size_t         eb  = (size_t)b * CRF_S;

        float acc = 0.0f;
        int   cnt = 0;
        for (int s = l; s < CRF_S; s += 32) {
            const int  t = tg[(eb + s) << tsh];
            const bool m = (mkp[(eb + s) << msh] != 0);
            if (m) {
                cnt++;
                if (s < CRF_S - 1) acc += lg[(size_t)s * CRF_T + t];
                if (s >= 1)        acc += trans[tg[(eb + s - 1) << tsh] * CRF_T + t];
            }
        }
#pragma unroll
        for (int o = 16; o; o >>= 1) {
            acc += __shfl_xor_sync(0xffffffffu, acc, o);
            cnt += __shfl_xor_sync(0xffffffffu, cnt, o);
        }
        if (l == 0) {
            acc += startT[tg[eb << tsh]];
            const int lt = tg[(eb + cnt - 1) << tsh];
            acc += endT[lt];
            if (mkp[(eb + CRF_S - 1) << msh]) acc += lg[(size_t)(CRF_S - 1) * CRF_T + lt];
            g_npart[b] = acc;
        }
    }

    // ---- last CTA performs the final deterministic reduction ----
    __syncthreads();
    if (tid == 0) {
        __threadfence();
        unsigned t = atomicAdd(&g_ticket, 1u);
        do_red = (t == gridDim.x - 1);
    }
    __syncthreads();
    if (do_red) {
        __threadfence();
        float a = 0.0f;
        for (int i = tid; i < CRF_B; i += 128)     // fixed order per thread
            a += g_npart[i] - g_dpart[i];
        rbuf[tid] = a;
        __syncthreads();
        for (int o = 64; o; o >>= 1) {
            if (tid < o) rbuf[tid] += rbuf[tid + o];
            __syncthreads();
        }
        if (tid == 0) { out[0] = rbuf[0]; g_ticket = 0u; }
    }
}

extern "C" void kernel_launch(void* const* d_in, const int* in_sizes, int n_in,
                              void* d_out, int out_size)
{
    const float* logits = (const float*)d_in[0];
    const void*  tags   = d_in[1];
    const void*  mask   = d_in[2];
    const float* trans  = (const float*)d_in[3];
    const float* startT = (const float*)d_in[4];
    const float* endT   = (const float*)d_in[5];
    float*       out    = (float*)d_out;

    crf_main<<<CRF_B / 4, 128>>>(logits, tags, mask, trans, startT, endT, out);
}

// round 7
// speedup vs baseline: 1.6731x; 1.6731x over previous
#include <cuda_runtime.h>
#include <cstdint>

#define CRF_B 512
#define CRF_S 512
#define CRF_T 64

// Per-batch partial results + completion ticket (device scratch; no allocs).
__device__ float    g_dpart[CRF_B];
__device__ float    g_npart[CRF_B];
__device__ unsigned g_ticket;   // zero-init; last CTA resets it each run

typedef unsigned long long u64;

// ---- packed f32x2 helpers (sm_100+ PTX) ----
__device__ __forceinline__ u64 ffma2(u64 a, u64 b, u64 c) {
    u64 d;
    asm("fma.rn.f32x2 %0, %1, %2, %3;" : "=l"(d) : "l"(a), "l"(b), "l"(c));
    return d;
}
__device__ __forceinline__ u64 fadd2(u64 a, u64 b) {
    u64 d;
    asm("add.rn.f32x2 %0, %1, %2;" : "=l"(d) : "l"(a), "l"(b));
    return d;
}
__device__ __forceinline__ u64 pack2(float x, float y) {
    u64 d;
    asm("mov.b64 %0, {%1, %2};" : "=l"(d) : "f"(x), "f"(y));
    return d;
}
__device__ __forceinline__ float2 unpack2(u64 a) {
    float2 r;
    asm("mov.b64 {%0, %1}, %2;" : "=f"(r.x), "=f"(r.y) : "l"(a));
    return r;
}

// Warp-uniform layout detection (ballot => uniform, no global state).
__device__ __forceinline__ int detect_mshift(const void* mask, int l) {
    const unsigned* mw = (const unsigned*)mask;
    unsigned bad = ((mw[l] | mw[l + 32]) & 0xFFFFFF00u) ? 1u : 0u;
    return __ballot_sync(0xffffffffu, bad) ? 0 : 2;   // u8 : i32
}
__device__ __forceinline__ int detect_tshift(const void* tags, int l) {
    const unsigned* tw = (const unsigned*)tags;
    unsigned odd = tw[2 * l + 1] ? 1u : 0u;
    return __ballot_sync(0xffffffffu, odd) ? 0 : 1;   // i32 : i64
}

// ============================================================================
// Single fused kernel: 128 blocks x 160 threads.
//   Warps 0-3: forward recurrence (denominator), batch = 4*blockIdx.x + w.
//   Warp 4:    numerator (gold-path) for the block's 4 batches.
//   Last CTA to finish: deterministic final reduction.
//
// Forward: lane l owns states j=2l,2l+1; E=exp(trans) in registers (64 f32x2);
// p in per-warp ping-pong smem duplicated ({p,p}) so broadcast LDS.128 feeds
// fma.rn.f32x2 directly. Exp-domain recurrence; exact power-of-2 renorm every
// 4 steps via a single-lane exponent broadcast (1 shfl).
// Manual 2x-unrolled step bodies give static ping-pong indices and renamed
// FIFO rotation WITHOUT the register blowup of unroll 4 (R6 spilled: regs=238,
// L1 ~50% from LDL/STL traffic -> 172us; R4's clean loop was 109us).
// ============================================================================
__global__ void __launch_bounds__(160, 1) crf_main(
    const float* __restrict__ logits,
    const void* __restrict__ tagsv,
    const void* __restrict__ maskv,
    const float* __restrict__ trans,
    const float* __restrict__ startT,
    const float* __restrict__ endT,
    float* __restrict__ out)
{
    __shared__ __align__(16) u64 pdup[4][2][CRF_T];
    __shared__ float rbuf[256];
    __shared__ int   do_red;

    const int tid = threadIdx.x;
    const int w   = tid >> 5;
    const int l   = tid & 31;

    const int msh = detect_mshift(maskv, l);

    if (w == 4) {
        // ---------------- Numerator warp ----------------
        const int tsh = detect_tshift(tagsv, l);
        const int*           tg  = (const int*)tagsv;
        const unsigned char* mkp = (const unsigned char*)maskv;

        for (int q = 0; q < 4; q++) {
            const int    b  = blockIdx.x * 4 + q;
            const float* lg = logits + (size_t)b * (CRF_S * CRF_T);
            const size_t eb = (size_t)b * CRF_S;

            float acc = 0.0f;
            int   cnt = 0;
            for (int s = l; s < CRF_S; s += 32) {
                const int  t = tg[(eb + s) << tsh];
                const bool m = (mkp[(eb + s) << msh] != 0);
                if (m) {
                    cnt++;
                    if (s < CRF_S - 1) acc += lg[(size_t)s * CRF_T + t];
                    if (s >= 1)        acc += trans[tg[(eb + s - 1) << tsh] * CRF_T + t];
                }
            }
#pragma unroll
            for (int o = 16; o; o >>= 1) {
                acc += __shfl_xor_sync(0xffffffffu, acc, o);
                cnt += __shfl_xor_sync(0xffffffffu, cnt, o);
            }
            if (l == 0) {
                acc += startT[tg[eb << tsh]];
                const int lt = tg[(eb + cnt - 1) << tsh];
                acc += endT[lt];
                if (mkp[(eb + CRF_S - 1) << msh]) acc += lg[(size_t)(CRF_S - 1) * CRF_T + lt];
                g_npart[b] = acc;
            }
        }
    } else {
        // ---------------- Forward warp ----------------
        const int b = blockIdx.x * 4 + w;

        u64 Ereg[64];
#pragma unroll
        for (int i = 0; i < 64; i++) {
            float2 t = ((const float2*)trans)[i * 32 + l];
            Ereg[i] = pack2(__expf(t.x), __expf(t.y));
        }

        const float*         lg = logits + (size_t)b * (CRF_S * CRF_T);
        const unsigned char* mk = (const unsigned char*)maskv + (((size_t)b * CRF_S) << msh);

        // init: alpha0 = start + logits[:,0,:]; exp-domain with offset C.
        float2 l0 = ((const float2*)lg)[l];
        float a0 = startT[2 * l]     + l0.x;
        float a1 = startT[2 * l + 1] + l0.y;
        float mx = fmaxf(a0, a1);
#pragma unroll
        for (int o = 16; o; o >>= 1) mx = fmaxf(mx, __shfl_xor_sync(0xffffffffu, mx, o));
        float C  = mx;
        float p0 = __expf(a0 - mx);
        float p1 = __expf(a1 - mx);
        ((ulonglong2*)pdup[w][0])[l] = make_ulonglong2(pack2(p0, p0), pack2(p1, p1));

        // prologue: 4-deep logits/mask register FIFO + current-step exp.
        float2 f1 = ((const float2*)(lg + 1 * CRF_T))[l];
        float2 f2 = ((const float2*)(lg + 2 * CRF_T))[l];
        float2 f3 = ((const float2*)(lg + 3 * CRF_T))[l];
        float2 f4 = ((const float2*)(lg + 4 * CRF_T))[l];
        float2 f5 = ((const float2*)(lg + 5 * CRF_T))[l];
        unsigned char m2 = mk[(size_t)2 << msh];
        unsigned char m3 = mk[(size_t)3 << msh];
        unsigned char m4 = mk[(size_t)4 << msh];
        unsigned char m5 = mk[(size_t)5 << msh];
        float e0 = __expf(f1.x);
        float e1 = __expf(f1.y);
        unsigned char cm = mk[(size_t)1 << msh];
        __syncwarp();

        // One recurrence step: read src (prev p), write dst (new p).
        auto step = [&](int s, const u64* src, u64* dst) {
            // GEMV: 32 broadcast LDS.128, 64 FFMA2, 8 chains.
            const ulonglong2* pd2 = (const ulonglong2*)src;
            u64 a0v = 0ull, a1v = 0ull, a2v = 0ull, a3v = 0ull;
            u64 a4v = 0ull, a5v = 0ull, a6v = 0ull, a7v = 0ull;
#pragma unroll
            for (int k = 0; k < 64; k += 8) {
                ulonglong2 q0 = pd2[(k >> 1) + 0];
                ulonglong2 q1 = pd2[(k >> 1) + 1];
                ulonglong2 q2 = pd2[(k >> 1) + 2];
                ulonglong2 q3 = pd2[(k >> 1) + 3];
                a0v = ffma2(Ereg[k + 0], q0.x, a0v);
                a1v = ffma2(Ereg[k + 1], q0.y, a1v);
                a2v = ffma2(Ereg[k + 2], q1.x, a2v);
                a3v = ffma2(Ereg[k + 3], q1.y, a3v);
                a4v = ffma2(Ereg[k + 4], q2.x, a4v);
                a5v = ffma2(Ereg[k + 5], q2.y, a5v);
                a6v = ffma2(Ereg[k + 6], q3.x, a6v);
                a7v = ffma2(Ereg[k + 7], q3.y, a7v);
            }

            // FIFO rotate (renamed under the 2x body) + clamped prefetch.
            const float2 head      = f2;
            const unsigned char mh = m2;
            f2 = f3; m2 = m3;
            f3 = f4; m3 = m4;
            f4 = f5; m4 = m5;
            const int sp = (s + 5 < CRF_S) ? (s + 5) : (CRF_S - 1);
            f5 = ((const float2*)(lg + (size_t)sp * CRF_T))[l];
            m5 = mk[(size_t)sp << msh];
            const float ne0 = __expf(head.x);
            const float ne1 = __expf(head.y);

            u64 tot = fadd2(fadd2(fadd2(a0v, a1v), fadd2(a2v, a3v)),
                            fadd2(fadd2(a4v, a5v), fadd2(a6v, a7v)));
            float2 sum = unpack2(tot);
            const float pn0 = sum.x * e0;
            const float pn1 = sum.y * e1;
            if (cm) { p0 = pn0; p1 = pn1; }     // mask: keep old alpha if 0

            // Exact power-of-2 renorm every 4 steps: lane-0 exponent broadcast
            // (1 shfl). Scaling is exact; only magnitude containment needed.
            if ((s & 3) == 0) {
                int e = (__float_as_int(p0) >> 23) & 255;
                e = __shfl_sync(0xffffffffu, e, 0);
                float scale = __int_as_float((254 - e) << 23);   // 2^(127-e)
                p0 *= scale;
                p1 *= scale;
                C += (float)(e - 127) * 0.6931471805599453f;
            }

            ((ulonglong2*)dst)[l] = make_ulonglong2(pack2(p0, p0), pack2(p1, p1));
            e0 = ne0; e1 = ne1; cm = mh;
            __syncwarp();
        };

        // s = 1..510 in pairs (static ping-pong), tail s = 511.
        for (int s = 1; s < CRF_S - 1; s += 2) {
            step(s,     pdup[w][0], pdup[w][1]);
            step(s + 1, pdup[w][1], pdup[w][0]);
        }
        step(CRF_S - 1, pdup[w][0], pdup[w][1]);

        // denom = C + log(sum_j p_j * exp(end_j))
        float v = p0 * __expf(endT[2 * l]) + p1 * __expf(endT[2 * l + 1]);
#pragma unroll
        for (int o = 16; o; o >>= 1) v += __shfl_xor_sync(0xffffffffu, v, o);
        if (l == 0) g_dpart[b] = C + logf(v);
    }

    // ---- last CTA performs the final deterministic reduction ----
    __syncthreads();
    if (tid == 0) {
        __threadfence();
        unsigned t = atomicAdd(&g_ticket, 1u);
        do_red = (t == gridDim.x - 1);
    }
    __syncthreads();
    if (do_red) {
        __threadfence();
        float a = 0.0f;
        for (int i = tid; i < CRF_B; i += 160)     // fixed order per thread
            a += g_npart[i] - g_dpart[i];
        rbuf[tid] = a;
        if (tid < 96) rbuf[160 + tid] = 0.0f;
        __syncthreads();
        for (int o = 128; o; o >>= 1) {
            if (tid < o) rbuf[tid] += rbuf[tid + o];
            __syncthreads();
        }
        if (tid == 0) { out[0] = rbuf[0]; g_ticket = 0u; }
    }
}

extern "C" void kernel_launch(void* const* d_in, const int* in_sizes, int n_in,
                              void* d_out, int out_size)
{
    const float* logits = (const float*)d_in[0];
    const void*  tags   = d_in[1];
    const void*  mask   = d_in[2];
    const float* trans  = (const float*)d_in[3];
    const float* startT = (const float*)d_in[4];
    const float* endT   = (const float*)d_in[5];
    float*       out    = (float*)d_out;

    crf_main<<<CRF_B / 4, 160>>>(logits, tags, mask, trans, startT, endT, out);
}

// round 8
// speedup vs baseline: 1.9510x; 1.1661x over previous
#include <cuda_runtime.h>
#include <cstdint>

#define CRF_B 512
#define CRF_S 512
#define CRF_T 64

// Per-batch partial results + completion ticket (device scratch; no allocs).
__device__ float    g_dpart[CRF_B];
__device__ float    g_npart[CRF_B];
__device__ unsigned g_ticket;   // zero-init; last CTA resets it each run

typedef unsigned long long u64;

// ---- packed f32x2 helpers (sm_100+ PTX) ----
__device__ __forceinline__ u64 ffma2(u64 a, u64 b, u64 c) {
    u64 d;
    asm("fma.rn.f32x2 %0, %1, %2, %3;" : "=l"(d) : "l"(a), "l"(b), "l"(c));
    return d;
}
__device__ __forceinline__ u64 fadd2(u64 a, u64 b) {
    u64 d;
    asm("add.rn.f32x2 %0, %1, %2;" : "=l"(d) : "l"(a), "l"(b));
    return d;
}
__device__ __forceinline__ u64 pack2(float x, float y) {
    u64 d;
    asm("mov.b64 %0, {%1, %2};" : "=l"(d) : "f"(x), "f"(y));
    return d;
}
__device__ __forceinline__ float2 unpack2(u64 a) {
    float2 r;
    asm("mov.b64 {%0, %1}, %2;" : "=f"(r.x), "=f"(r.y) : "l"(a));
    return r;
}

// Warp-uniform layout detection (ballot => uniform, no global state).
__device__ __forceinline__ int detect_mshift(const void* mask, int l) {
    const unsigned* mw = (const unsigned*)mask;
    unsigned bad = ((mw[l] | mw[l + 32]) & 0xFFFFFF00u) ? 1u : 0u;
    return __ballot_sync(0xffffffffu, bad) ? 0 : 2;   // u8 : i32
}
__device__ __forceinline__ int detect_tshift(const void* tags, int l) {
    const unsigned* tw = (const unsigned*)tags;
    unsigned odd = tw[2 * l + 1] ? 1u : 0u;
    return __ballot_sync(0xffffffffu, odd) ? 0 : 1;   // i32 : i64
}

// ============================================================================
// Single fused kernel: 128 blocks x 160 threads.
//   Warps 0-3: forward recurrence (denominator), batch = 4*blockIdx.x + w.
//   Warp 4:    numerator (gold-path) for the block's 4 batches.
//   Last CTA to finish: deterministic final reduction.
//
// Forward, i-PACKED scheme (R8): lane l owns states j0=2l, j1=2l+1 and stores
// its pair NATURALLY packed {p_j0,p_j1} (one u64 per lane, one STS.64).
// Accumulators pack along i: acc_j = {sum_{even i}, sum_{odd i}}, so the
// broadcast operand is exactly the packed pairs other lanes stored -> only
// 16 broadcast LDS.128 per step (was 32 with j-packing + duplication), and
// ~60 fewer live registers so the loads can stay in flight.
// E = exp(trans) in registers: EA[k]={E[2k][j0],E[2k+1][j0]}, EB likewise j1.
// Exp-domain recurrence; exact power-of-2 renorm every 4 steps (1 shfl).
// ============================================================================
__global__ void __launch_bounds__(160, 1) crf_main(
    const float* __restrict__ logits,
    const void* __restrict__ tagsv,
    const void* __restrict__ maskv,
    const float* __restrict__ trans,
    const float* __restrict__ startT,
    const float* __restrict__ endT,
    float* __restrict__ out)
{
    __shared__ __align__(16) u64 psm[4][2][32];   // packed {p_2l, p_2l+1}
    __shared__ float rbuf[256];
    __shared__ int   do_red;

    const int tid = threadIdx.x;
    const int w   = tid >> 5;
    const int l   = tid & 31;

    const int msh = detect_mshift(maskv, l);

    if (w == 4) {
        // ---------------- Numerator warp ----------------
        const int tsh = detect_tshift(tagsv, l);
        const int*           tg  = (const int*)tagsv;
        const unsigned char* mkp = (const unsigned char*)maskv;

        for (int q = 0; q < 4; q++) {
            const int    b  = blockIdx.x * 4 + q;
            const float* lg = logits + (size_t)b * (CRF_S * CRF_T);
            const size_t eb = (size_t)b * CRF_S;

            float acc = 0.0f;
            int   cnt = 0;
            for (int s = l; s < CRF_S; s += 32) {
                const int  t = tg[(eb + s) << tsh];
                const bool m = (mkp[(eb + s) << msh] != 0);
                if (m) {
                    cnt++;
                    if (s < CRF_S - 1) acc += lg[(size_t)s * CRF_T + t];
                    if (s >= 1)        acc += trans[tg[(eb + s - 1) << tsh] * CRF_T + t];
                }
            }
#pragma unroll
            for (int o = 16; o; o >>= 1) {
                acc += __shfl_xor_sync(0xffffffffu, acc, o);
                cnt += __shfl_xor_sync(0xffffffffu, cnt, o);
            }
            if (l == 0) {
                acc += startT[tg[eb << tsh]];
                const int lt = tg[(eb + cnt - 1) << tsh];
                acc += endT[lt];
                if (mkp[(eb + CRF_S - 1) << msh]) acc += lg[(size_t)(CRF_S - 1) * CRF_T + lt];
                g_npart[b] = acc;
            }
        }
    } else {
        // ---------------- Forward warp ----------------
        const int b  = blockIdx.x * 4 + w;
        const int j0 = 2 * l;

        // E pairs along i for this lane's two columns j0, j0+1.
        u64 EA[32], EB[32];
#pragma unroll
        for (int k = 0; k < 32; k++) {
            const float* r0 = trans + (size_t)(2 * k)     * CRF_T + j0;
            const float* r1 = trans + (size_t)(2 * k + 1) * CRF_T + j0;
            EA[k] = pack2(__expf(r0[0]), __expf(r1[0]));
            EB[k] = pack2(__expf(r0[1]), __expf(r1[1]));
        }

        const float*         lg = logits + (size_t)b * (CRF_S * CRF_T);
        const unsigned char* mk = (const unsigned char*)maskv + (((size_t)b * CRF_S) << msh);

        // init: alpha0 = start + logits[:,0,:]; exp-domain with offset C.
        float2 l0 = ((const float2*)lg)[l];
        float a0 = startT[j0]     + l0.x;
        float a1 = startT[j0 + 1] + l0.y;
        float mx = fmaxf(a0, a1);
#pragma unroll
        for (int o = 16; o; o >>= 1) mx = fmaxf(mx, __shfl_xor_sync(0xffffffffu, mx, o));
        float C  = mx;
        float p0 = __expf(a0 - mx);
        float p1 = __expf(a1 - mx);
        psm[w][0][l] = pack2(p0, p1);

        // prologue: 4-deep logits/mask register FIFO + current-step exp.
        float2 f1 = ((const float2*)(lg + 1 * CRF_T))[l];
        float2 f2 = ((const float2*)(lg + 2 * CRF_T))[l];
        float2 f3 = ((const float2*)(lg + 3 * CRF_T))[l];
        float2 f4 = ((const float2*)(lg + 4 * CRF_T))[l];
        float2 f5 = ((const float2*)(lg + 5 * CRF_T))[l];
        unsigned char m2 = mk[(size_t)2 << msh];
        unsigned char m3 = mk[(size_t)3 << msh];
        unsigned char m4 = mk[(size_t)4 << msh];
        unsigned char m5 = mk[(size_t)5 << msh];
        float e0 = __expf(f1.x);
        float e1 = __expf(f1.y);
        unsigned char cm = mk[(size_t)1 << msh];
        __syncwarp();

        // One recurrence step: read src (prev p, packed), write dst (new p).
        auto step = [&](int s, const u64* src, u64* dst) {
            const ulonglong2* q2 = (const ulonglong2*)src;
            // 16 broadcast LDS.128; 64 FFMA2 in 4 chains (2 per j, depth 16).
            u64 aA0 = 0ull, aA1 = 0ull, aB0 = 0ull, aB1 = 0ull;
#pragma unroll
            for (int m = 0; m < 16; m++) {
                ulonglong2 q = q2[m];              // {pairs for i=4m..4m+1, i=4m+2..4m+3}
                aA0 = ffma2(EA[2 * m],     q.x, aA0);
                aB0 = ffma2(EB[2 * m],     q.x, aB0);
                aA1 = ffma2(EA[2 * m + 1], q.y, aA1);
                aB1 = ffma2(EB[2 * m + 1], q.y, aB1);
            }

            // FIFO rotate (renamed under the 2x body) + clamped prefetch.
            const float2 head      = f2;
            const unsigned char mh = m2;
            f2 = f3; m2 = m3;
            f3 = f4; m3 = m4;
            f4 = f5; m4 = m5;
            const int sp = (s + 5 < CRF_S) ? (s + 5) : (CRF_S - 1);
            f5 = ((const float2*)(lg + (size_t)sp * CRF_T))[l];
            m5 = mk[(size_t)sp << msh];
            const float ne0 = __expf(head.x);
            const float ne1 = __expf(head.y);

            float2 sA = unpack2(fadd2(aA0, aA1));
            float2 sB = unpack2(fadd2(aB0, aB1));
            const float pn0 = (sA.x + sA.y) * e0;
            const float pn1 = (sB.x + sB.y) * e1;
            if (cm) { p0 = pn0; p1 = pn1; }     // mask: keep old alpha if 0

            // Exact power-of-2 renorm every 4 steps: lane-0 exponent broadcast
            // (1 shfl). Scaling is exact; only magnitude containment needed.
            if ((s & 3) == 0) {
                int e = (__float_as_int(p0) >> 23) & 255;
                e = __shfl_sync(0xffffffffu, e, 0);
                float scale = __int_as_float((254 - e) << 23);   // 2^(127-e)
                p0 *= scale;
                p1 *= scale;
                C += (float)(e - 127) * 0.6931471805599453f;
            }

            dst[l] = pack2(p0, p1);
            e0 = ne0; e1 = ne1; cm = mh;
            __syncwarp();
        };

        // s = 1..510 in pairs (static ping-pong), tail s = 511.
        for (int s = 1; s < CRF_S - 1; s += 2) {
            step(s,     psm[w][0], psm[w][1]);
            step(s + 1, psm[w][1], psm[w][0]);
        }
        step(CRF_S - 1, psm[w][0], psm[w][1]);

        // denom = C + log(sum_j p_j * exp(end_j))
        float v = p0 * __expf(endT[j0]) + p1 * __expf(endT[j0 + 1]);
#pragma unroll
        for (int o = 16; o; o >>= 1) v += __shfl_xor_sync(0xffffffffu, v, o);
        if (l == 0) g_dpart[b] = C + logf(v);
    }

    // ---- last CTA performs the final deterministic reduction ----
    __syncthreads();
    if (tid == 0) {
        __threadfence();
        unsigned t = atomicAdd(&g_ticket, 1u);
        do_red = (t == gridDim.x - 1);
    }
    __syncthreads();
    if (do_red) {
        __threadfence();
        float a = 0.0f;
        for (int i = tid; i < CRF_B; i += 160)     // fixed order per thread
            a += g_npart[i] - g_dpart[i];
        rbuf[tid] = a;
        if (tid < 96) rbuf[160 + tid] = 0.0f;
        __syncthreads();
        for (int o = 128; o; o >>= 1) {
            if (tid < o) rbuf[tid] += rbuf[tid + o];
            __syncthreads();
        }
        if (tid == 0) { out[0] = rbuf[0]; g_ticket = 0u; }
    }
}

extern "C" void kernel_launch(void* const* d_in, const int* in_sizes, int n_in,
                              void* d_out, int out_size)
{
    const float* logits = (const float*)d_in[0];
    const void*  tags   = d_in[1];
    const void*  mask   = d_in[2];
    const float* trans  = (const float*)d_in[3];
    const float* startT = (const float*)d_in[4];
    const float* endT   = (const float*)d_in[5];
    float*       out    = (float*)d_out;

    crf_main<<<CRF_B / 4, 160>>>(logits, tags, mask, trans, startT, endT, out);
}